// round 11
// baseline (speedup 1.0000x reference)
#include <cuda_runtime.h>

#define CHUNK  512
#define MAXW   20
#define MAXN   (MAXW * CHUNK)   // 10240
#define MAXP   1000
#define SB     4096
#define KCAP   1536              // 999 + 512 < 1536

typedef unsigned long long u64;

// ---- static device scratch (no allocations allowed) ----
__device__ u64    g_maskT[(size_t)MAXW * MAXN * 8];  // [word][row][8] suppression bits
__device__ u64    g_diag[(size_t)MAXN * 8];          // diagonal-tile masks, 8 u64/row
__device__ float4 g_sboxes[MAXN];                    // boxes in sorted order
__device__ float  g_sscores[MAXN];                   // scores in sorted order
__device__ u64    g_keep[MAXW * 8];                  // keep bits (8 words per chunk)
__device__ int    g_prefixw[MAXW * 8];               // rank base per 64-bit word
__device__ int    g_base[SB];                        // bucket base (descending order)
__device__ int    g_members[MAXN];                   // indices grouped by bucket

__device__ __forceinline__ int bucket_of(float s) {
    int b = (int)(s * 4096.0f);           // monotone for s >= 0
    return max(0, min(SB - 1, b));
}

// ---------------------------------------------------------------------------
// S1: fused single-block sort front-end: histogram + descending exclusive
// scan + bucket fill. All bucket state in shared (no cross-replay cleanup).
// ---------------------------------------------------------------------------
__global__ void k_sortA(const float* __restrict__ scores, int N) {
    __shared__ int s_cnt[SB];
    __shared__ int s_base[SB];
    __shared__ int wsum[32];
    int tid = threadIdx.x, lane = tid & 31, wid = tid >> 5;

    for (int b = tid; b < SB; b += 1024) s_cnt[b] = 0;
    __syncthreads();
    for (int i = tid; i < N; i += 1024)
        atomicAdd(&s_cnt[bucket_of(scores[i])], 1);
    __syncthreads();

    int cbase = 0;
    for (int k = 0; k < SB / 1024; k++) {
        int b = SB - 1 - (k * 1024 + tid);   // descending bucket order
        int v = s_cnt[b];
        int x = v;
        #pragma unroll
        for (int o = 1; o < 32; o <<= 1) {
            int y = __shfl_up_sync(~0u, x, o);
            if (lane >= o) x += y;
        }
        if (lane == 31) wsum[wid] = x;
        __syncthreads();
        if (wid == 0) {
            int s = wsum[lane];
            #pragma unroll
            for (int o = 1; o < 32; o <<= 1) {
                int y = __shfl_up_sync(~0u, s, o);
                if (lane >= o) s += y;
            }
            wsum[lane] = s;
        }
        __syncthreads();
        s_base[b] = cbase + (x - v) + (wid ? wsum[wid - 1] : 0);
        cbase += wsum[31];
        __syncthreads();
    }

    for (int b = tid; b < SB; b += 1024) { s_cnt[b] = 0; g_base[b] = s_base[b]; }
    __syncthreads();
    for (int i = tid; i < N; i += 1024) {
        int b = bucket_of(scores[i]);
        int slot = s_base[b] + atomicAdd(&s_cnt[b], 1);
        g_members[slot] = i;
    }
}

// ---------------------------------------------------------------------------
// S2: exact stable rank within bucket + scatter (grid-parallel).
// ---------------------------------------------------------------------------
__global__ void k_place(const float4* __restrict__ boxes,
                        const float* __restrict__ scores, int N) {
    int i = blockIdx.x * blockDim.x + threadIdx.x;
    if (i >= N) return;
    float si = scores[i];
    int b = bucket_of(si);
    int base = g_base[b];
    int cb   = ((b > 0) ? g_base[b - 1] : N) - base;
    int r = base;
    for (int t = 0; t < cb; t++) {
        int j = g_members[base + t];
        if (j == i) continue;
        float sj = scores[j];
        r += (sj > si) || (sj == si && j < i);
    }
    g_sboxes[r]  = boxes[i];
    g_sscores[r] = si;
}

// ---------------------------------------------------------------------------
// K2: pairwise IoU suppression bitmask, 512x512 tiles, upper triangle.
// suppress <=> IoU > 0.5 <=> 3*inter > areaR + areaC  (division-free).
// Padding boxes all-zero -> never suppress.
// ---------------------------------------------------------------------------
__global__ void k_mask(int N, int W) {
    int cb = blockIdx.x, rb = blockIdx.y;
    if (cb < rb) return;
    __shared__ float4 cbox[CHUNK];
    __shared__ float  carea[CHUNK];
    int t  = threadIdx.x;
    int cg = cb * CHUNK + t;
    float4 cv = (cg < N) ? g_sboxes[cg] : make_float4(0.f, 0.f, 0.f, 0.f);
    cbox[t]  = cv;
    carea[t] = (cv.z - cv.x) * (cv.w - cv.y);
    __syncthreads();

    int rg = rb * CHUNK + t;
    if (rg >= N) return;
    float4 r = g_sboxes[rg];
    float ra = (r.z - r.x) * (r.w - r.y);

    u64 m[8];
    #pragma unroll
    for (int q = 0; q < 8; q++) m[q] = 0ull;

    if (cb > rb) {
        #pragma unroll
        for (int q = 0; q < 8; q++) {
            u64 mm = 0ull;
            #pragma unroll 16
            for (int jj = 0; jj < 64; jj++) {
                int j = q * 64 + jj;
                float4 c = cbox[j];
                float ix1 = fmaxf(r.x, c.x), iy1 = fmaxf(r.y, c.y);
                float ix2 = fminf(r.z, c.z), iy2 = fminf(r.w, c.w);
                float inter = fmaxf(ix2 - ix1, 0.0f) * fmaxf(iy2 - iy1, 0.0f);
                if (3.0f * inter > ra + carea[j]) mm |= 1ull << jj;
            }
            m[q] = mm;
        }
    } else {
        // diagonal tile: only suppress later (lower-score) boxes j > t
        #pragma unroll 8
        for (int j = 0; j < CHUNK; j++) {
            if (j <= t) continue;
            float4 c = cbox[j];
            float ix1 = fmaxf(r.x, c.x), iy1 = fmaxf(r.y, c.y);
            float ix2 = fminf(r.z, c.z), iy2 = fminf(r.w, c.w);
            float inter = fmaxf(ix2 - ix1, 0.0f) * fmaxf(iy2 - iy1, 0.0f);
            if (3.0f * inter > ra + carea[j]) m[j >> 6] |= 1ull << (j & 63);
        }
        ulonglong2* dd = (ulonglong2*)(g_diag + ((size_t)rg << 3));
        #pragma unroll
        for (int q = 0; q < 4; q++) dd[q] = make_ulonglong2(m[2 * q], m[2 * q + 1]);
    }
    ulonglong2* dst = (ulonglong2*)(g_maskT + ((size_t)cb * MAXN + rg) * 8);
    #pragma unroll
    for (int q = 0; q < 4; q++) dst[q] = make_ulonglong2(m[2 * q], m[2 * q + 1]);
}

// ---------------------------------------------------------------------------
// phase A helpers
// ---------------------------------------------------------------------------
__device__ __forceinline__ u64 vmask64(int valid) {
    return (valid >= 64) ? ~0ull : ((valid <= 0) ? 0ull : ((1ull << valid) - 1ull));
}

__device__ __forceinline__ int ffs8(const u64* p) {
    int i = -1;
    #pragma unroll
    for (int q = 7; q >= 0; q--)
        if (p[q]) i = (q << 6) + __ffsll((long long)p[q]) - 1;
    return i;
}

__device__ __forceinline__ void ldrow(u64* d, const u64* dt, int i) {
    const ulonglong2* r = (const ulonglong2*)(dt + ((size_t)i << 3));
    #pragma unroll
    for (int q = 0; q < 4; q++) {
        ulonglong2 v = r[q];
        d[2 * q] = v.x; d[2 * q + 1] = v.y;
    }
}

// Serial greedy within one 512-chunk; pending p[8] in registers, diag rows
// from SMEM with speculative prefetch of the next candidate.
__device__ __forceinline__ int phaseA512(const u64* dt, u64* p, u64* k,
                                         int gbase, int* klist) {
    int n = 0;
    int i = ffs8(p);
    u64 dcur[8];
    if (i >= 0) ldrow(dcur, dt, i);
    while (i >= 0) {
        #pragma unroll
        for (int q = 0; q < 8; q++) {
            u64 bit = ((i >> 6) == q) ? (1ull << (i & 63)) : 0ull;
            k[q] |= bit;
            p[q] &= ~bit;
        }
        klist[n++] = gbase + i;
        int j = ffs8(p);                       // speculative next candidate
        u64 dnext[8];
        if (j >= 0) ldrow(dnext, dt, j);
        #pragma unroll
        for (int q = 0; q < 8; q++) p[q] &= ~dcur[q];
        int i2 = ffs8(p);
        if (i2 == j) {
            i = j;
            #pragma unroll
            for (int q = 0; q < 8; q++) dcur[q] = dnext[q];
        } else {
            i = i2;
            if (i2 >= 0) ldrow(dcur, dt, i2);
        }
    }
    return n;
}

// ---------------------------------------------------------------------------
// K3: lazy greedy scan over 512-wide chunks (19 rounds).
//   warps 0-5: gather OR over the full kept list of maskT[wc][kept_row]
//   warps 6-7: prefetch diag tile wc+1 into the other dynamic-smem buffer
//   thread 0 : OR 6 partials + phase A (registers + SMEM diag, speculated)
// Early termination once total kept >= MAXP.
// dynamic smem: diag[2][CHUNK*8] u64 + parts[6*8] u64 + klist[KCAP] int
// ---------------------------------------------------------------------------
__global__ void k_scan(int N, int W) {
    extern __shared__ u64 dyn[];
    u64* diagbuf = dyn;                        // 2 * CHUNK * 8 u64 = 64 KB
    u64* parts   = dyn + 2 * CHUNK * 8;        // 48 u64
    int* klist   = (int*)(parts + 48);         // KCAP ints
    __shared__ int s_stop, s_cstop, s_total, s_K;
    int tid = threadIdx.x, lane = tid & 31, wid = tid >> 5;

    // prologue: load diag tiles 0 and 1
    {
        const ulonglong2* src = (const ulonglong2*)g_diag;
        ulonglong2* d0 = (ulonglong2*)diagbuf;
        for (int e = tid; e < CHUNK * 4; e += 256) d0[e] = src[e];
        if (W > 1)
            for (int e = tid; e < CHUNK * 4; e += 256)
                d0[CHUNK * 4 + e] = src[CHUNK * 4 + e];
    }
    if (tid == 0) { s_stop = 0; s_cstop = W; s_total = 0; s_K = 0; }
    __syncthreads();

    // chunk 0
    if (tid == 0) {
        u64 p[8], k[8];
        int valid = min(N, CHUNK);
        #pragma unroll
        for (int q = 0; q < 8; q++) { p[q] = vmask64(valid - q * 64); k[q] = 0ull; }
        int n = phaseA512(diagbuf, p, k, 0, klist);
        int base = 0;
        #pragma unroll
        for (int q = 0; q < 8; q++) {
            g_keep[q] = k[q];
            g_prefixw[q] = base;
            base += __popcll(k[q]);
        }
        s_total = base; s_K = n;
        if (base >= MAXP) { s_stop = 1; s_cstop = 1; }
    }
    __syncthreads();

    for (int wc = 1; wc < W; wc++) {
        if (s_stop) break;
        int pb = wc & 1;
        int K = s_K;

        if (wid < 6) {
            // gather OR over ALL kept rows for word wc
            const u64* mp = g_maskT + (size_t)wc * (MAXN * 8);
            u64 a[8];
            #pragma unroll
            for (int q = 0; q < 8; q++) a[q] = 0ull;
            for (int t = tid; t < K; t += 192) {
                const ulonglong2* row =
                    (const ulonglong2*)(mp + ((size_t)klist[t] << 3));
                #pragma unroll
                for (int q = 0; q < 4; q++) {
                    ulonglong2 v = row[q];
                    a[2 * q] |= v.x; a[2 * q + 1] |= v.y;
                }
            }
            #pragma unroll
            for (int q = 0; q < 8; q++) {
                #pragma unroll
                for (int o = 16; o; o >>= 1)
                    a[q] |= __shfl_xor_sync(~0u, a[q], o);
            }
            if (lane == 0) {
                #pragma unroll
                for (int q = 0; q < 8; q++) parts[wid * 8 + q] = a[q];
            }
        } else {
            // warps 6,7: prefetch diag tile wc+1 into the other buffer
            if (wc + 1 < W) {
                const ulonglong2* src =
                    (const ulonglong2*)g_diag + (size_t)(wc + 1) * (CHUNK * 4);
                ulonglong2* dst =
                    (ulonglong2*)(diagbuf + (size_t)(pb ^ 1) * (CHUNK * 8));
                for (int e = tid - 192; e < CHUNK * 4; e += 64) dst[e] = src[e];
            }
        }
        __syncthreads();

        if (tid == 0) {
            u64 rem[8];
            #pragma unroll
            for (int q = 0; q < 8; q++) rem[q] = 0ull;
            #pragma unroll
            for (int w6 = 0; w6 < 6; w6++)
                #pragma unroll
                for (int q = 0; q < 8; q++) rem[q] |= parts[w6 * 8 + q];

            int valid = N - wc * CHUNK;
            u64 p[8], k[8];
            #pragma unroll
            for (int q = 0; q < 8; q++) {
                p[q] = ~rem[q] & vmask64(valid - q * 64);
                k[q] = 0ull;
            }
            int n = phaseA512(diagbuf + (size_t)pb * (CHUNK * 8), p, k,
                              wc * CHUNK, klist + K);
            int base = s_total;
            #pragma unroll
            for (int q = 0; q < 8; q++) {
                g_keep[wc * 8 + q] = k[q];
                g_prefixw[wc * 8 + q] = base;
                base += __popcll(k[q]);
            }
            s_total = base; s_K = K + n;
            if (base >= MAXP) { s_stop = 1; s_cstop = wc + 1; }
        }
        __syncthreads();
    }

    // chunks after the stop point can never contribute kept outputs
    int cstop = s_cstop;
    for (int idx = cstop * 8 + tid; idx < W * 8; idx += 256) g_keep[idx] = 0ull;
}

// ---------------------------------------------------------------------------
// K4: apply MAX_PROPOSALS cutoff and emit outputs:
//   out[0 : 4N) boxes | out[4N : 5N) scores | out[5N : 6N) keep as 0/1
// ---------------------------------------------------------------------------
__global__ void k_out(float* __restrict__ out, int N) {
    int p = blockIdx.x * blockDim.x + threadIdx.x;
    if (p >= N) return;
    int c  = p >> 9;
    int iw = (p >> 6) & 7;
    int ii = p & 63;
    u64 kw = g_keep[c * 8 + iw];
    bool kept = (kw >> ii) & 1ull;
    int r = g_prefixw[c * 8 + iw] + __popcll(kw & ((1ull << ii) - 1ull));
    bool fin = kept && (r < MAXP);

    float4 b = fin ? g_sboxes[p] : make_float4(0.f, 0.f, 0.f, 0.f);
    ((float4*)out)[p] = b;
    out[4 * N + p] = fin ? g_sscores[p] : 0.0f;
    out[5 * N + p] = fin ? 1.0f : 0.0f;
}

// ---------------------------------------------------------------------------
extern "C" void kernel_launch(void* const* d_in, const int* in_sizes, int n_in,
                              void* d_out, int out_size) {
    const float4* boxes  = (const float4*)d_in[0];
    const float*  scores = (const float*)d_in[1];
    int N = in_sizes[1];
    int W = (N + CHUNK - 1) / CHUNK;

    // dynamic smem for k_scan: diag double buffer + partials + klist
    const int scan_smem = (2 * CHUNK * 8 + 48) * 8 + KCAP * 4;   // 72,064 B
    cudaFuncSetAttribute(k_scan, cudaFuncAttributeMaxDynamicSharedMemorySize,
                         scan_smem);

    k_sortA<<<1, 1024>>>(scores, N);
    k_place<<<(N + 255) / 256, 256>>>(boxes, scores, N);

    dim3 g2(W, W);
    k_mask<<<g2, CHUNK>>>(N, W);

    k_scan<<<1, 256, scan_smem>>>(N, W);

    k_out<<<(N + 255) / 256, 256>>>((float*)d_out, N);
}

// round 12
// speedup vs baseline: 3.2235x; 3.2235x over previous
#include <cuda_runtime.h>

#define CHUNK  256
#define MAXW   40
#define MAXN   (MAXW * CHUNK)   // 10240
#define MAXP   1000
#define SB     4096
#define KCAP   1280              // stop fires by 1000 => K <= 999+256 < 1280

typedef unsigned long long u64;

// ---- static device scratch (no allocations allowed) ----
__device__ ulonglong4 g_maskT[(size_t)MAXW * MAXN];  // [word][row] 256-bit rows
__device__ ulonglong4 g_diag[MAXN];                  // diagonal-tile masks
__device__ float4     g_sboxes[MAXN];                // boxes in sorted order
__device__ float      g_sscores[MAXN];               // scores in sorted order
__device__ u64        g_keep[MAXW * 4];              // keep bits, 4 u64/chunk
__device__ int        g_prefixw[MAXW * 4];           // rank base per 64-bit word
__device__ int        g_base[SB];                    // bucket base (descending)
__device__ int        g_members[MAXN];               // indices grouped by bucket

__device__ __forceinline__ int bucket_of(float s) {
    int b = (int)(s * 4096.0f);           // monotone for s >= 0
    return max(0, min(SB - 1, b));
}

// ---------------------------------------------------------------------------
// S1: fused single-block sort front-end: histogram + descending exclusive
// scan + bucket fill. All bucket state in shared (no cross-replay cleanup).
// ---------------------------------------------------------------------------
__global__ void k_sortA(const float* __restrict__ scores, int N) {
    __shared__ int s_cnt[SB];
    __shared__ int s_base[SB];
    __shared__ int wsum[32];
    int tid = threadIdx.x, lane = tid & 31, wid = tid >> 5;

    for (int b = tid; b < SB; b += 1024) s_cnt[b] = 0;
    __syncthreads();
    for (int i = tid; i < N; i += 1024)
        atomicAdd(&s_cnt[bucket_of(scores[i])], 1);
    __syncthreads();

    int cbase = 0;
    for (int k = 0; k < SB / 1024; k++) {
        int b = SB - 1 - (k * 1024 + tid);   // descending bucket order
        int v = s_cnt[b];
        int x = v;
        #pragma unroll
        for (int o = 1; o < 32; o <<= 1) {
            int y = __shfl_up_sync(~0u, x, o);
            if (lane >= o) x += y;
        }
        if (lane == 31) wsum[wid] = x;
        __syncthreads();
        if (wid == 0) {
            int s = wsum[lane];
            #pragma unroll
            for (int o = 1; o < 32; o <<= 1) {
                int y = __shfl_up_sync(~0u, s, o);
                if (lane >= o) s += y;
            }
            wsum[lane] = s;
        }
        __syncthreads();
        s_base[b] = cbase + (x - v) + (wid ? wsum[wid - 1] : 0);
        cbase += wsum[31];
        __syncthreads();
    }

    for (int b = tid; b < SB; b += 1024) { s_cnt[b] = 0; g_base[b] = s_base[b]; }
    __syncthreads();
    for (int i = tid; i < N; i += 1024) {
        int b = bucket_of(scores[i]);
        int slot = s_base[b] + atomicAdd(&s_cnt[b], 1);
        g_members[slot] = i;
    }
}

// ---------------------------------------------------------------------------
// S2: exact stable rank within bucket + scatter (grid-parallel).
// ---------------------------------------------------------------------------
__global__ void k_place(const float4* __restrict__ boxes,
                        const float* __restrict__ scores, int N) {
    int i = blockIdx.x * blockDim.x + threadIdx.x;
    if (i >= N) return;
    float si = scores[i];
    int b = bucket_of(si);
    int base = g_base[b];
    int cb   = ((b > 0) ? g_base[b - 1] : N) - base;
    int r = base;
    for (int t = 0; t < cb; t++) {
        int j = g_members[base + t];
        if (j == i) continue;
        float sj = scores[j];
        r += (sj > si) || (sj == si && j < i);
    }
    g_sboxes[r]  = boxes[i];
    g_sscores[r] = si;
}

// ---------------------------------------------------------------------------
// K2: pairwise IoU suppression bitmask, 256x256 tiles, upper triangle.
// suppress <=> IoU > 0.5 <=> 3*inter > areaR + areaC  (division-free).
// Padding boxes all-zero -> never suppress.
// ---------------------------------------------------------------------------
__global__ void k_mask(int N, int W) {
    int cb = blockIdx.x, rb = blockIdx.y;
    if (cb < rb) return;
    __shared__ float4 cbox[CHUNK];
    __shared__ float  carea[CHUNK];
    int t  = threadIdx.x;
    int cg = cb * CHUNK + t;
    float4 cv = (cg < N) ? g_sboxes[cg] : make_float4(0.f, 0.f, 0.f, 0.f);
    cbox[t]  = cv;
    carea[t] = (cv.z - cv.x) * (cv.w - cv.y);
    __syncthreads();

    int rg = rb * CHUNK + t;
    if (rg >= N) return;
    float4 r = g_sboxes[rg];
    float ra = (r.z - r.x) * (r.w - r.y);

    u64 m[4] = {0ull, 0ull, 0ull, 0ull};
    if (cb > rb) {
        #pragma unroll
        for (int q = 0; q < 4; q++) {
            u64 mm = 0ull;
            #pragma unroll 32
            for (int jj = 0; jj < 64; jj++) {
                int j = q * 64 + jj;
                float4 c = cbox[j];
                float ix1 = fmaxf(r.x, c.x), iy1 = fmaxf(r.y, c.y);
                float ix2 = fminf(r.z, c.z), iy2 = fminf(r.w, c.w);
                float inter = fmaxf(ix2 - ix1, 0.0f) * fmaxf(iy2 - iy1, 0.0f);
                if (3.0f * inter > ra + carea[j]) mm |= 1ull << jj;
            }
            m[q] = mm;
        }
    } else {
        // diagonal tile: only suppress later (lower-score) boxes j > t
        #pragma unroll 4
        for (int j = 0; j < CHUNK; j++) {
            if (j <= t) continue;
            float4 c = cbox[j];
            float ix1 = fmaxf(r.x, c.x), iy1 = fmaxf(r.y, c.y);
            float ix2 = fminf(r.z, c.z), iy2 = fminf(r.w, c.w);
            float inter = fmaxf(ix2 - ix1, 0.0f) * fmaxf(iy2 - iy1, 0.0f);
            if (3.0f * inter > ra + carea[j]) m[j >> 6] |= 1ull << (j & 63);
        }
        g_diag[rg] = make_ulonglong4(m[0], m[1], m[2], m[3]);
    }
    g_maskT[(size_t)cb * MAXN + rg] = make_ulonglong4(m[0], m[1], m[2], m[3]);
}

// ---------------------------------------------------------------------------
// phase helpers
// ---------------------------------------------------------------------------
__device__ __forceinline__ u64 vmask64(int valid) {
    return (valid >= 64) ? ~0ull : ((valid <= 0) ? 0ull : ((1ull << valid) - 1ull));
}

// R7's proven 2-word serial greedy with speculative diag prefetch.
// Local row i's ulonglong2 lives at base[2*i] (base pre-offset selects
// lo-words of rows 0..127 or hi-words of rows 128..255).
__device__ __forceinline__ int phaseA128(const ulonglong2* base, u64 p0, u64 p1,
                                         int gbase, int* klist,
                                         u64& k0o, u64& k1o) {
    u64 k0 = 0ull, k1 = 0ull;
    int n = 0;
    int i = p0 ? (__ffsll((long long)p0) - 1)
               : (p1 ? 64 + __ffsll((long long)p1) - 1 : -1);
    ulonglong2 dd = (i >= 0) ? base[2 * i] : make_ulonglong2(0ull, 0ull);
    while (i >= 0) {
        if (i < 64) { k0 |= 1ull << i; p0 &= ~(1ull << i); }
        else        { k1 |= 1ull << (i - 64); p1 &= ~(1ull << (i - 64)); }
        klist[n++] = gbase + i;
        int j = p0 ? (__ffsll((long long)p0) - 1)
                   : (p1 ? 64 + __ffsll((long long)p1) - 1 : -1);
        ulonglong2 ddj = (j >= 0) ? base[2 * j] : make_ulonglong2(0ull, 0ull);
        p0 &= ~dd.x; p1 &= ~dd.y;
        int i2 = p0 ? (__ffsll((long long)p0) - 1)
                    : (p1 ? 64 + __ffsll((long long)p1) - 1 : -1);
        if (i2 == j) { i = j; dd = ddj; }
        else { i = i2; if (i2 >= 0) dd = base[2 * i2]; }
    }
    k0o = k0; k1o = k1;
    return n;
}

// Hierarchical 256-bit phase A: two 128-bit sub-phases bridged by one
// batched (independent-load) application of sub0-kept hi-words.
__device__ __forceinline__ int phase256(const ulonglong4* diag,
                                        u64 r0, u64 r1, u64 r2, u64 r3,
                                        int valid, int gbase, int* klist,
                                        u64* kw) {
    const ulonglong2* dd = (const ulonglong2*)diag;
    // sub-chunk 0: rows 0..127, words 0-1 at dd[2*i]
    int n0 = phaseA128(dd, ~r0 & vmask64(valid), ~r1 & vmask64(valid - 64),
                       gbase, klist, kw[0], kw[1]);
    // bridge: OR hi-words (z,w at dd[2*i+1]) of sub0 kept into rem2/rem3
    {
        int t = 0;
        for (; t + 4 <= n0; t += 4) {
            ulonglong2 a = dd[2 * (klist[t + 0] - gbase) + 1];
            ulonglong2 b = dd[2 * (klist[t + 1] - gbase) + 1];
            ulonglong2 c = dd[2 * (klist[t + 2] - gbase) + 1];
            ulonglong2 d = dd[2 * (klist[t + 3] - gbase) + 1];
            r2 |= a.x | b.x | c.x | d.x;
            r3 |= a.y | b.y | c.y | d.y;
        }
        for (; t < n0; t++) {
            ulonglong2 a = dd[2 * (klist[t] - gbase) + 1];
            r2 |= a.x; r3 |= a.y;
        }
    }
    // sub-chunk 1: rows 128..255, words 2-3 at dd[2*(128+i)+1] = (dd+257)[2*i]
    int n1 = phaseA128(dd + 257, ~r2 & vmask64(valid - 128),
                       ~r3 & vmask64(valid - 192),
                       gbase + 128, klist + n0, kw[2], kw[3]);
    return n0 + n1;
}

// ---------------------------------------------------------------------------
// K3: lazy greedy scan over 256-wide chunks (39 rounds), R7 round structure.
//   all 256 threads: gather OR over full kept list of maskT[wc][kept_row]
//   thread 0: reduce partials + hierarchical phase A
//   tid >= 128: prefetch diag tile wc+1 (double-buffered) concurrently
// Early termination once total kept >= MAXP.
// ---------------------------------------------------------------------------
__global__ void k_scan(int N, int W) {
    __shared__ ulonglong4 diagbuf[2][CHUNK];   // 16 KB
    __shared__ ulonglong4 s_part[8];
    __shared__ int s_klist[KCAP];
    __shared__ int s_K, s_stop, s_cstop, s_total;
    int tid = threadIdx.x, lane = tid & 31, wid = tid >> 5;
    ulonglong4 Z4 = make_ulonglong4(0ull, 0ull, 0ull, 0ull);

    diagbuf[0][tid] = (tid < N) ? g_diag[tid] : Z4;
    {
        int g = CHUNK + tid;
        diagbuf[1][tid] = (W > 1 && g < N) ? g_diag[g] : Z4;
    }
    if (tid == 0) { s_stop = 0; s_cstop = W; s_total = 0; s_K = 0; }
    __syncthreads();

    // chunk 0
    if (tid == 0) {
        u64 kw[4];
        int n = phase256(diagbuf[0], 0ull, 0ull, 0ull, 0ull,
                         min(N, CHUNK), 0, s_klist, kw);
        int base = 0;
        #pragma unroll
        for (int q = 0; q < 4; q++) {
            g_keep[q] = kw[q];
            g_prefixw[q] = base;
            base += __popcll(kw[q]);
        }
        s_total = base; s_K = n;
        if (base >= MAXP) { s_stop = 1; s_cstop = 1; }
    }
    __syncthreads();

    for (int wc = 1; wc < W; wc++) {
        if (s_stop) break;
        int pb = wc & 1;
        int K = s_K;

        // phase 1: cooperative gather of chunk wc's 256-bit suppression word
        const ulonglong4* mp = g_maskT + (size_t)wc * MAXN;
        u64 a0 = 0, a1 = 0, a2 = 0, a3 = 0;
        for (int t = tid; t < K; t += 256) {
            ulonglong4 v = mp[s_klist[t]];
            a0 |= v.x; a1 |= v.y; a2 |= v.z; a3 |= v.w;
        }
        #pragma unroll
        for (int o = 16; o; o >>= 1) {
            a0 |= __shfl_xor_sync(~0u, a0, o);
            a1 |= __shfl_xor_sync(~0u, a1, o);
            a2 |= __shfl_xor_sync(~0u, a2, o);
            a3 |= __shfl_xor_sync(~0u, a3, o);
        }
        if (lane == 0) s_part[wid] = make_ulonglong4(a0, a1, a2, a3);
        __syncthreads();

        // phase 2: thread 0 reduce + phase A; tid>=128 prefetch diag wc+1
        if (tid == 0) {
            u64 r0 = 0, r1 = 0, r2 = 0, r3 = 0;
            #pragma unroll
            for (int p = 0; p < 8; p++) {
                ulonglong4 v = s_part[p];
                r0 |= v.x; r1 |= v.y; r2 |= v.z; r3 |= v.w;
            }
            u64 kw[4];
            int n = phase256(diagbuf[pb], r0, r1, r2, r3, N - wc * CHUNK,
                             wc * CHUNK, s_klist + K, kw);
            int base = s_total;
            #pragma unroll
            for (int q = 0; q < 4; q++) {
                g_keep[wc * 4 + q] = kw[q];
                g_prefixw[wc * 4 + q] = base;
                base += __popcll(kw[q]);
            }
            s_total = base; s_K = K + n;
            if (base >= MAXP) { s_stop = 1; s_cstop = wc + 1; }
        } else if (tid >= 128 && wc + 1 < W) {
            int t = tid - 128;          // 0..127, two rows each
            int g0 = (wc + 1) * CHUNK + t;
            int g1 = g0 + 128;
            diagbuf[pb ^ 1][t]       = (g0 < N) ? g_diag[g0] : Z4;
            diagbuf[pb ^ 1][t + 128] = (g1 < N) ? g_diag[g1] : Z4;
        }
        __syncthreads();
    }

    // chunks after the stop point can never contribute kept outputs
    int cstop = s_cstop;
    for (int idx = cstop * 4 + tid; idx < W * 4; idx += 256) g_keep[idx] = 0ull;
}

// ---------------------------------------------------------------------------
// K4: apply MAX_PROPOSALS cutoff and emit outputs:
//   out[0 : 4N) boxes | out[4N : 5N) scores | out[5N : 6N) keep as 0/1
// ---------------------------------------------------------------------------
__global__ void k_out(float* __restrict__ out, int N) {
    int p = blockIdx.x * blockDim.x + threadIdx.x;
    if (p >= N) return;
    int widx = p >> 6;        // global 64-bit word index == (chunk*4 + word)
    int ii   = p & 63;
    u64 kw = g_keep[widx];
    bool kept = (kw >> ii) & 1ull;
    int r = g_prefixw[widx] + __popcll(kw & ((1ull << ii) - 1ull));
    bool fin = kept && (r < MAXP);

    float4 b = fin ? g_sboxes[p] : make_float4(0.f, 0.f, 0.f, 0.f);
    ((float4*)out)[p] = b;
    out[4 * N + p] = fin ? g_sscores[p] : 0.0f;
    out[5 * N + p] = fin ? 1.0f : 0.0f;
}

// ---------------------------------------------------------------------------
extern "C" void kernel_launch(void* const* d_in, const int* in_sizes, int n_in,
                              void* d_out, int out_size) {
    const float4* boxes  = (const float4*)d_in[0];
    const float*  scores = (const float*)d_in[1];
    int N = in_sizes[1];
    int W = (N + CHUNK - 1) / CHUNK;

    k_sortA<<<1, 1024>>>(scores, N);
    k_place<<<(N + 255) / 256, 256>>>(boxes, scores, N);

    dim3 g2(W, W);
    k_mask<<<g2, CHUNK>>>(N, W);

    k_scan<<<1, 256>>>(N, W);

    k_out<<<(N + 255) / 256, 256>>>((float*)d_out, N);
}

// round 13
// speedup vs baseline: 5.5991x; 1.7369x over previous
#include <cuda_runtime.h>

#define CHUNK  128
#define MAXW   79
#define MAXN   (MAXW * CHUNK)   // 10112
#define MAXP   1000
#define SB     4096
#define KCAP   1280              // stop fires by 1000 => K <= 1127 < 1280

typedef unsigned long long u64;

// ---- static device scratch (no allocations allowed) ----
__device__ ulonglong2 g_maskT[(size_t)MAXW * MAXN];  // [word][row] suppression bits
__device__ ulonglong2 g_diag[MAXN];                  // diagonal-block masks
__device__ float4     g_sboxes[MAXN];                // boxes in sorted order
__device__ float      g_sscores[MAXN];               // scores in sorted order
__device__ ulonglong2 g_keep[MAXW];                  // keep bits per 128-chunk
__device__ int        g_prefix[MAXW];                // kept-count prefix per chunk
__device__ int        g_base[SB];                    // bucket base (descending order)
__device__ int        g_members[MAXN];               // indices grouped by bucket

__device__ __forceinline__ int bucket_of(float s) {
    int b = (int)(s * 4096.0f);           // monotone for s >= 0
    return max(0, min(SB - 1, b));
}

// ---------------------------------------------------------------------------
// S1: fused single-block sort front-end: histogram + descending exclusive
// scan + bucket fill. All bucket state in shared (no cross-replay cleanup).
// ---------------------------------------------------------------------------
__global__ void k_sortA(const float* __restrict__ scores, int N) {
    __shared__ int s_cnt[SB];
    __shared__ int s_base[SB];
    __shared__ int wsum[32];
    int tid = threadIdx.x, lane = tid & 31, wid = tid >> 5;

    for (int b = tid; b < SB; b += 1024) s_cnt[b] = 0;
    __syncthreads();
    for (int i = tid; i < N; i += 1024)
        atomicAdd(&s_cnt[bucket_of(scores[i])], 1);
    __syncthreads();

    int cbase = 0;
    for (int k = 0; k < SB / 1024; k++) {
        int b = SB - 1 - (k * 1024 + tid);   // descending bucket order
        int v = s_cnt[b];
        int x = v;
        #pragma unroll
        for (int o = 1; o < 32; o <<= 1) {
            int y = __shfl_up_sync(~0u, x, o);
            if (lane >= o) x += y;
        }
        if (lane == 31) wsum[wid] = x;
        __syncthreads();
        if (wid == 0) {
            int s = wsum[lane];
            #pragma unroll
            for (int o = 1; o < 32; o <<= 1) {
                int y = __shfl_up_sync(~0u, s, o);
                if (lane >= o) s += y;
            }
            wsum[lane] = s;
        }
        __syncthreads();
        s_base[b] = cbase + (x - v) + (wid ? wsum[wid - 1] : 0);
        cbase += wsum[31];
        __syncthreads();
    }

    for (int b = tid; b < SB; b += 1024) { s_cnt[b] = 0; g_base[b] = s_base[b]; }
    __syncthreads();
    for (int i = tid; i < N; i += 1024) {
        int b = bucket_of(scores[i]);
        int slot = s_base[b] + atomicAdd(&s_cnt[b], 1);
        g_members[slot] = i;
    }
}

// ---------------------------------------------------------------------------
// S2: exact stable rank within bucket + scatter (grid-parallel).
// ---------------------------------------------------------------------------
__global__ void k_place(const float4* __restrict__ boxes,
                        const float* __restrict__ scores, int N) {
    int i = blockIdx.x * blockDim.x + threadIdx.x;
    if (i >= N) return;
    float si = scores[i];
    int b = bucket_of(si);
    int base = g_base[b];
    int cb   = ((b > 0) ? g_base[b - 1] : N) - base;
    int r = base;
    for (int t = 0; t < cb; t++) {
        int j = g_members[base + t];
        if (j == i) continue;
        float sj = scores[j];
        r += (sj > si) || (sj == si && j < i);
    }
    g_sboxes[r]  = boxes[i];
    g_sscores[r] = si;
}

// ---------------------------------------------------------------------------
// K2: pairwise IoU suppression bitmask, 128x128 tiles, upper triangle.
// suppress <=> IoU > 0.5 <=> 3*inter > areaR + areaC  (division-free).
// Stores TRANSPOSED: g_maskT[word][row].
// ---------------------------------------------------------------------------
__global__ void k_mask(int N, int W) {
    int cb = blockIdx.x, rb = blockIdx.y;
    if (cb < rb) return;
    __shared__ float4 cbox[CHUNK];
    __shared__ float  carea[CHUNK];
    int t  = threadIdx.x;
    int cg = cb * CHUNK + t;
    float4 cv = (cg < N) ? g_sboxes[cg] : make_float4(0.f, 0.f, 0.f, 0.f);
    cbox[t]  = cv;
    carea[t] = (cv.z - cv.x) * (cv.w - cv.y);
    __syncthreads();

    int rg = rb * CHUNK + t;
    if (rg >= N) return;
    float4 r = g_sboxes[rg];
    float ra = (r.z - r.x) * (r.w - r.y);

    u64 m0 = 0, m1 = 0;
    if (cb > rb) {
        #pragma unroll 32
        for (int j = 0; j < 64; j++) {
            float4 c = cbox[j];
            float ix1 = fmaxf(r.x, c.x), iy1 = fmaxf(r.y, c.y);
            float ix2 = fminf(r.z, c.z), iy2 = fminf(r.w, c.w);
            float inter = fmaxf(ix2 - ix1, 0.0f) * fmaxf(iy2 - iy1, 0.0f);
            if (3.0f * inter > ra + carea[j]) m0 |= 1ull << j;
        }
        #pragma unroll 32
        for (int j = 64; j < 128; j++) {
            float4 c = cbox[j];
            float ix1 = fmaxf(r.x, c.x), iy1 = fmaxf(r.y, c.y);
            float ix2 = fminf(r.z, c.z), iy2 = fminf(r.w, c.w);
            float inter = fmaxf(ix2 - ix1, 0.0f) * fmaxf(iy2 - iy1, 0.0f);
            if (3.0f * inter > ra + carea[j]) m1 |= 1ull << (j - 64);
        }
    } else {
        #pragma unroll 32
        for (int j = 0; j < 128; j++) {
            if (j <= t) continue;  // diagonal: only suppress later boxes
            float4 c = cbox[j];
            float ix1 = fmaxf(r.x, c.x), iy1 = fmaxf(r.y, c.y);
            float ix2 = fminf(r.z, c.z), iy2 = fminf(r.w, c.w);
            float inter = fmaxf(ix2 - ix1, 0.0f) * fmaxf(iy2 - iy1, 0.0f);
            if (3.0f * inter > ra + carea[j]) {
                if (j < 64) m0 |= 1ull << j; else m1 |= 1ull << (j - 64);
            }
        }
        g_diag[rg] = make_ulonglong2(m0, m1);
    }
    g_maskT[(size_t)cb * MAXN + rg] = make_ulonglong2(m0, m1);
}

__device__ __forceinline__ u64 vmask64(int valid) {
    return (valid >= 64) ? ~0ull : ((valid <= 0) ? 0ull : ((1ull << valid) - 1ull));
}

// ---------------------------------------------------------------------------
// phase A, optimistic batch version.
// Tentatively keep ALL pending bits; batch-OR their diag rows (independent
// LDS, pipelined); if (OR & pending)==0, the whole chunk is resolved in one
// pass (~92% of chunks). Otherwise bits below the first conflicted bit f are
// provably kept, f is provably suppressed; re-batch the rest (rare).
// Appends kept global row ids to klist, returns count.
// ---------------------------------------------------------------------------
__device__ __forceinline__ int phaseA_opt(const ulonglong2* d, u64 r0, u64 r1,
                                          int valid, int gbase, int* klist,
                                          u64& k0o, u64& k1o) {
    u64 P0 = ~r0 & vmask64(valid);
    u64 P1 = ~r1 & vmask64(valid - 64);
    u64 c0 = 0ull, c1 = 0ull;          // confirmed kept
    u64 sup0 = 0ull, sup1 = 0ull;      // suppression by confirmed kept
    int n = 0;
    while (P0 | P1) {
        int nck = n;                   // klist checkpoint
        u64 o0 = 0ull, o1 = 0ull;
        u64 t = P0;
        while (t) {
            int i = __ffsll((long long)t) - 1; t &= t - 1ull;
            klist[n++] = gbase + i;
            ulonglong2 dd = d[i];
            o0 |= dd.x; o1 |= dd.y;
        }
        t = P1;
        while (t) {
            int i = __ffsll((long long)t) - 1; t &= t - 1ull;
            klist[n++] = gbase + 64 + i;
            ulonglong2 dd = d[64 + i];
            o0 |= dd.x; o1 |= dd.y;
        }
        u64 x0 = (sup0 | o0) & P0, x1 = (sup1 | o1) & P1;
        if (!(x0 | x1)) { c0 |= P0; c1 |= P1; break; }   // happy path

        // conflict: first conflicted bit f
        n = nck;                       // rewind klist
        int f = x0 ? (__ffsll((long long)x0) - 1)
                   : (64 + __ffsll((long long)x1) - 1);
        u64 m0, m1;                    // mask of bits strictly below f
        if (f < 64) { m0 = (1ull << f) - 1ull; m1 = 0ull; }
        else        { m0 = ~0ull;             m1 = (1ull << (f - 64)) - 1ull; }
        u64 nc0 = P0 & m0, nc1 = P1 & m1;     // newly confirmed
        c0 |= nc0; c1 |= nc1;
        t = nc0;
        while (t) {
            int i = __ffsll((long long)t) - 1; t &= t - 1ull;
            klist[n++] = gbase + i;
            ulonglong2 dd = d[i];
            sup0 |= dd.x; sup1 |= dd.y;
        }
        t = nc1;
        while (t) {
            int i = __ffsll((long long)t) - 1; t &= t - 1ull;
            klist[n++] = gbase + 64 + i;
            ulonglong2 dd = d[64 + i];
            sup0 |= dd.x; sup1 |= dd.y;
        }
        // drop confirmed + suppressed (incl. f) from pending; iterate
        P0 = P0 & ~m0 & ~sup0;
        P1 = P1 & ~m1 & ~sup1;
        if (f < 64) P0 &= ~(1ull << f); else P1 &= ~(1ull << (f - 64));
    }
    k0o = c0; k1o = c1;
    return n;
}

// ---------------------------------------------------------------------------
// K3: lazy greedy scan (R7 round structure + optimistic phase A).
//   phase 1: ALL 256 threads gather OR over the global kept list of
//            maskT[wc][kept_row]  (<=5 independent loads/thread, 8 warps).
//   phase 2: thread 0 reduces partials + runs phase A; threads 128..255
//            prefetch diag tile wc+1 concurrently (double-buffered).
// Early termination once total kept >= MAXP.
// ---------------------------------------------------------------------------
__global__ void k_scan(int N, int W) {
    __shared__ ulonglong2 diagbuf[2][CHUNK];
    __shared__ ulonglong2 s_part[8];
    __shared__ int s_klist[KCAP];
    __shared__ int s_K, s_stop, s_cstop, s_total;
    int tid = threadIdx.x, lane = tid & 31, wid = tid >> 5;

    if (tid < CHUNK) {
        diagbuf[0][tid] = (tid < N) ? g_diag[tid] : make_ulonglong2(0ull, 0ull);
    } else {
        int g = CHUNK + (tid - CHUNK);
        diagbuf[1][tid - CHUNK] = (W > 1 && g < N) ? g_diag[g] : make_ulonglong2(0ull, 0ull);
    }
    if (tid == 0) { s_stop = 0; s_cstop = W; s_total = 0; s_K = 0; }
    __syncthreads();

    // chunk 0
    if (tid == 0) {
        u64 k0, k1;
        int n = phaseA_opt(diagbuf[0], 0ull, 0ull, min(N, CHUNK), 0,
                           s_klist, k0, k1);
        g_keep[0] = make_ulonglong2(k0, k1);
        g_prefix[0] = 0;
        int tot = __popcll(k0) + __popcll(k1);
        s_total = tot; s_K = n;
        if (tot >= MAXP) { s_stop = 1; s_cstop = 1; }
    }
    __syncthreads();

    for (int c = 0; c + 1 < W; c++) {
        if (s_stop) break;
        int wc = c + 1;
        int K = s_K;

        // phase 1: cooperative gather of chunk wc's suppression word
        const ulonglong2* mp = g_maskT + (size_t)wc * MAXN;
        u64 ax = 0ull, ay = 0ull;
        for (int t = tid; t < K; t += 256) {
            ulonglong2 v = mp[s_klist[t]];
            ax |= v.x; ay |= v.y;
        }
        #pragma unroll
        for (int o = 16; o; o >>= 1) {
            ax |= __shfl_xor_sync(~0u, ax, o);
            ay |= __shfl_xor_sync(~0u, ay, o);
        }
        if (lane == 0) s_part[wid] = make_ulonglong2(ax, ay);
        __syncthreads();

        // phase 2: thread 0 reduce + phase A; tid>=128 prefetch diag c+2
        if (tid == 0) {
            u64 r0 = 0ull, r1 = 0ull;
            #pragma unroll
            for (int p = 0; p < 8; p++) {
                ulonglong2 v = s_part[p];
                r0 |= v.x; r1 |= v.y;
            }
            u64 k0, k1;
            int n = phaseA_opt(diagbuf[wc & 1], r0, r1, N - wc * CHUNK,
                               wc * CHUNK, s_klist + K, k0, k1);
            g_keep[wc] = make_ulonglong2(k0, k1);
            g_prefix[wc] = s_total;
            int tot = s_total + __popcll(k0) + __popcll(k1);
            s_total = tot; s_K = K + n;
            if (tot >= MAXP) { s_stop = 1; s_cstop = wc + 1; }
        } else if (tid >= 128 && c + 2 < W) {
            int g = (c + 2) * CHUNK + (tid - 128);
            diagbuf[c & 1][tid - 128] =
                (g < N) ? g_diag[g] : make_ulonglong2(0ull, 0ull);
        }
        __syncthreads();
    }

    int cstop = s_cstop;
    for (int c2 = cstop + tid; c2 < W; c2 += 256)
        g_keep[c2] = make_ulonglong2(0ull, 0ull);
}

// ---------------------------------------------------------------------------
// K4: apply MAX_PROPOSALS cutoff and emit outputs:
//   out[0 : 4N) boxes | out[4N : 5N) scores | out[5N : 6N) keep as 0/1
// ---------------------------------------------------------------------------
__global__ void k_out(float* __restrict__ out, int N) {
    int p = blockIdx.x * blockDim.x + threadIdx.x;
    if (p >= N) return;
    int c = p >> 7, i = p & 127;
    ulonglong2 kw = g_keep[c];
    bool kept;
    int below;
    if (i < 64) {
        kept  = (kw.x >> i) & 1ull;
        below = __popcll(kw.x & ((1ull << i) - 1ull));
    } else {
        int ii = i - 64;
        kept  = (kw.y >> ii) & 1ull;
        below = __popcll(kw.x) + __popcll(kw.y & ((1ull << ii) - 1ull));
    }
    int r = g_prefix[c] + below;
    bool fin = kept && (r < MAXP);

    float4 b = fin ? g_sboxes[p] : make_float4(0.f, 0.f, 0.f, 0.f);
    ((float4*)out)[p] = b;
    out[4 * N + p] = fin ? g_sscores[p] : 0.0f;
    out[5 * N + p] = fin ? 1.0f : 0.0f;
}

// ---------------------------------------------------------------------------
extern "C" void kernel_launch(void* const* d_in, const int* in_sizes, int n_in,
                              void* d_out, int out_size) {
    const float4* boxes  = (const float4*)d_in[0];
    const float*  scores = (const float*)d_in[1];
    int N = in_sizes[1];
    int W = (N + CHUNK - 1) / CHUNK;

    k_sortA<<<1, 1024>>>(scores, N);
    k_place<<<(N + 255) / 256, 256>>>(boxes, scores, N);

    dim3 g2(W, W);
    k_mask<<<g2, CHUNK>>>(N, W);

    k_scan<<<1, 256>>>(N, W);

    k_out<<<(N + 255) / 256, 256>>>((float*)d_out, N);
}